// round 2
// baseline (speedup 1.0000x reference)
#include <cuda_runtime.h>
#include <stdint.h>

using u64t = unsigned long long;
#define DI __device__ __forceinline__

// ---------------- problem dims ----------------
constexpr int CE = 1024;      // C_emb
constexpr int T_ = 2048;      // T
constexpr int B_ = 16;        // batch
constexpr int KC = 4096;      // codebook size
constexpr int CC = 64;        // C_cb
constexpr int NTOK = B_ * T_; // 32768

// ---------------- output layout (float elements) ----------------
constexpr long long OFF_QUANT = 32768;                       // after codes
constexpr long long OFF_LOSS  = OFF_QUANT + (long long)B_ * CE * T_;   // 33587200
constexpr long long OFF_XPROJ = OFF_LOSS + 2;                // 33587202
constexpr long long OFF_QPROJ = OFF_XPROJ + (long long)B_ * CC * T_;   // 35684354

// ---------------- scratch (__device__ globals; no allocation) ----------------
__device__ float g_Win_t[CE * CC];    // [i][o]  1024 x 64
__device__ float g_Wout_t[CC * CE];   // [c][o]  64 x 1024
__device__ float g_cbn_t[CC * KC];    // [c][k]  64 x 4096
__device__ float g_cc2[KC];           // ||cbn_k||^2
__device__ float g_lossP[256];        // per-block loss partials

// ---------------- packed fp32x2 helpers ----------------
DI u64t pack2(float a, float b) {
    u64t r;
    asm("mov.b64 %0, {%1, %2};" : "=l"(r)
        : "r"(__float_as_uint(a)), "r"(__float_as_uint(b)));
    return r;
}
DI float2 unpack2(u64t v) {
    unsigned int lo, hi;
    asm("mov.b64 {%0, %1}, %2;" : "=r"(lo), "=r"(hi) : "l"(v));
    return make_float2(__uint_as_float(lo), __uint_as_float(hi));
}
DI void fma2(u64t& d, u64t a, u64t b) {
    asm("fma.rn.f32x2 %0, %1, %2, %0;" : "+l"(d) : "l"(a), "l"(b));
}
DI u64t add2(u64t a, u64t b) {
    u64t r;
    asm("add.rn.f32x2 %0, %1, %2;" : "=l"(r) : "l"(a), "l"(b));
    return r;
}

// ============================================================================
// Kernel 1a: W_in^T  — one block per output row o (64 blocks)
// W_in[o,i] = g_in[o]*v_in[o,i]/||v_in[o,:]||, stored transposed [i][o]
// ============================================================================
__global__ void k_win(const float* __restrict__ v_in, const float* __restrict__ g_in) {
    __shared__ float rb[256];
    int o = blockIdx.x, tid = threadIdx.x;
    float s = 0.f;
    for (int i = tid; i < CE; i += 256) {
        float v = v_in[o * CE + i];
        s = fmaf(v, v, s);
    }
    rb[tid] = s; __syncthreads();
    for (int st = 128; st >= 1; st >>= 1) {
        if (tid < st) rb[tid] += rb[tid + st];
        __syncthreads();
    }
    float nrm = sqrtf(rb[0]);
    float g = g_in[o];
    for (int i = tid; i < CE; i += 256) {
        g_Win_t[i * CC + o] = g * v_in[o * CE + i] / nrm;
    }
}

// ============================================================================
// Kernel 1b: W_out^T — one warp per row o (1024 warps = 128 blocks x 8 warps)
// W_out[o,c] = g_out[o]*v_out[o,c]/||v_out[o,:]||, stored transposed [c][o]
// ============================================================================
__global__ void k_wout(const float* __restrict__ v_out, const float* __restrict__ g_out) {
    int tid = threadIdx.x;
    int o = blockIdx.x * 8 + (tid >> 5);
    int lane = tid & 31;
    float a = v_out[o * CC + lane];
    float b = v_out[o * CC + lane + 32];
    float s = a * a + b * b;
    #pragma unroll
    for (int m = 16; m >= 1; m >>= 1) s += __shfl_xor_sync(0xffffffffu, s, m);
    float nrm = sqrtf(s);
    float g = g_out[o];
    g_Wout_t[lane * CE + o]        = g * a / nrm;
    g_Wout_t[(lane + 32) * CE + o] = g * b / nrm;
}

// ============================================================================
// Kernel 1c: normalized codebook transposed [c][k] + ||cbn_k||^2
// block handles 64 rows (64 blocks)
// ============================================================================
__global__ void k_cbn(const float* __restrict__ cbk) {
    __shared__ float s[64 * 65];
    int tid = threadIdx.x;
    int k0 = blockIdx.x * 64;
    for (int e = tid; e < 4096; e += 256) {
        int r = e >> 6, c = e & 63;
        s[r * 65 + c] = cbk[(k0 + r) * CC + c];
    }
    __syncthreads();
    if (tid < 64) {
        int r = tid;
        float ss = 0.f;
        #pragma unroll 8
        for (int c = 0; c < 64; c++) { float v = s[r * 65 + c]; ss = fmaf(v, v, ss); }
        float n = fmaxf(sqrtf(ss), 1e-12f);
        float cc = 0.f;
        #pragma unroll 8
        for (int c = 0; c < 64; c++) {
            float v = s[r * 65 + c] / n;
            s[r * 65 + c] = v;
            cc = fmaf(v, v, cc);
        }
        g_cc2[k0 + r] = cc;
    }
    __syncthreads();
    for (int e = tid; e < 4096; e += 256) {
        int c = e >> 6, r = e & 63;
        g_cbn_t[c * KC + k0 + r] = s[r * 65 + c];
    }
}

// ============================================================================
// Kernel 2: x_proj = W_in @ x   (per batch: 64x2048 = 64x1024 @ 1024x2048)
// grid (16 t-tiles, 16 b), block 256. Tile: 64o x 128t, K chunked by 64.
// Chunked accumulation (16 partials) for accuracy.
// ============================================================================
__global__ void k_gemm_in(const float* __restrict__ x, float* dout) {
    __shared__ float sW[64 * 64];   // [k][o]
    __shared__ float sX[64 * 128];  // [k][t]
    int b = blockIdx.y, tid = threadIdx.x;
    int tg0 = blockIdx.x * 128;
    int o0 = (tid >> 5) * 8;
    int t0 = (tid & 31) * 4;

    u64t tot[8][2], acc[8][2];
    #pragma unroll
    for (int i = 0; i < 8; i++) { tot[i][0] = 0; tot[i][1] = 0; acc[i][0] = 0; acc[i][1] = 0; }

    for (int kt = 0; kt < CE; kt += 64) {
        __syncthreads();
        for (int e = tid; e < 4096; e += 256) {
            // e = kk*64 + o
            sW[e] = g_Win_t[(kt + (e >> 6)) * CC + (e & 63)];
        }
        for (int e = tid; e < 8192; e += 256) {
            int kk = e >> 7, t = e & 127;
            sX[e] = x[(long long)b * CE * T_ + (long long)(kt + kk) * T_ + tg0 + t];
        }
        __syncthreads();
        #pragma unroll 8
        for (int k = 0; k < 64; k++) {
            float4 xa = *(const float4*)&sX[k * 128 + t0];
            u64t xb0 = pack2(xa.x, xa.y), xb1 = pack2(xa.z, xa.w);
            float4 w0 = *(const float4*)&sW[k * 64 + o0];
            float4 w1 = *(const float4*)&sW[k * 64 + o0 + 4];
            float wv[8] = {w0.x, w0.y, w0.z, w0.w, w1.x, w1.y, w1.z, w1.w};
            #pragma unroll
            for (int i = 0; i < 8; i++) {
                u64t wb = pack2(wv[i], wv[i]);
                fma2(acc[i][0], wb, xb0);
                fma2(acc[i][1], wb, xb1);
            }
        }
        #pragma unroll
        for (int i = 0; i < 8; i++) {
            tot[i][0] = add2(tot[i][0], acc[i][0]); acc[i][0] = 0;
            tot[i][1] = add2(tot[i][1], acc[i][1]); acc[i][1] = 0;
        }
    }
    #pragma unroll
    for (int i = 0; i < 8; i++) {
        float2 p0 = unpack2(tot[i][0]);
        float2 p1 = unpack2(tot[i][1]);
        long long base = OFF_XPROJ + (long long)b * CC * T_ + (long long)(o0 + i) * T_ + tg0 + t0;
        *(float2*)&dout[base]     = p0;
        *(float2*)&dout[base + 2] = p1;
    }
}

// ============================================================================
// Kernel 3: scoring + fused argmin. grid 256 (128 tokens each), block 256.
// e = x_proj / max(||x_proj||,eps) per token (token-uniform scale — argmin-safe).
// score_k = cc2[k] - 2*dot(e, cbn_k); running argmin, tie -> lower k.
// ============================================================================
__global__ void k_score(float* dout) {
    __shared__ float se[64 * 128];  // [c][t]
    __shared__ float sc[64 * 64];   // [c][k] chunk; reused for sinv + reduction
    int tid = threadIdx.x;
    int tokg = blockIdx.x * 128;
    int b = tokg >> 11;
    int t0g = tokg & (T_ - 1);
    const float* xp = dout + OFF_XPROJ + (long long)b * CC * T_;

    for (int e = tid; e < 8192; e += 256) {
        int c = e >> 7, t = e & 127;
        se[e] = xp[c * T_ + t0g + t];
    }
    __syncthreads();
    float* sinv = sc;
    if (tid < 128) {
        float s = 0.f;
        #pragma unroll 8
        for (int c = 0; c < 64; c++) { float v = se[c * 128 + tid]; s = fmaf(v, v, s); }
        sinv[tid] = 1.f / fmaxf(sqrtf(s), 1e-12f);
    }
    __syncthreads();
    for (int e = tid; e < 8192; e += 256) se[e] *= sinv[e & 127];

    int ktid = tid & 15, ttid = tid >> 4;
    int to0 = ttid * 8, kk0 = ktid * 4;
    float bestv[8]; int besti[8];
    #pragma unroll
    for (int i = 0; i < 8; i++) { bestv[i] = __int_as_float(0x7f800000); besti[i] = 0; }

    for (int kc = 0; kc < KC; kc += 64) {
        __syncthreads();
        for (int e = tid; e < 4096; e += 256) {
            // e = c*64 + k
            sc[e] = g_cbn_t[(e >> 6) * KC + kc + (e & 63)];
        }
        __syncthreads();
        u64t acc[8][2];
        #pragma unroll
        for (int i = 0; i < 8; i++) { acc[i][0] = 0; acc[i][1] = 0; }
        #pragma unroll 8
        for (int c = 0; c < 64; c++) {
            float4 cbv = *(const float4*)&sc[c * 64 + kk0];
            u64t cb0 = pack2(cbv.x, cbv.y), cb1 = pack2(cbv.z, cbv.w);
            float4 e0 = *(const float4*)&se[c * 128 + to0];
            float4 e1 = *(const float4*)&se[c * 128 + to0 + 4];
            float ev[8] = {e0.x, e0.y, e0.z, e0.w, e1.x, e1.y, e1.z, e1.w};
            #pragma unroll
            for (int i = 0; i < 8; i++) {
                u64t eb = pack2(ev[i], ev[i]);
                fma2(acc[i][0], eb, cb0);
                fma2(acc[i][1], eb, cb1);
            }
        }
        float4 cc = *(const float4*)&g_cc2[kc + kk0];
        #pragma unroll
        for (int i = 0; i < 8; i++) {
            float2 d0 = unpack2(acc[i][0]);
            float2 d1 = unpack2(acc[i][1]);
            float s0 = fmaf(-2.f, d0.x, cc.x);
            float s1 = fmaf(-2.f, d0.y, cc.y);
            float s2 = fmaf(-2.f, d1.x, cc.z);
            float s3 = fmaf(-2.f, d1.y, cc.w);
            int kbase = kc + kk0;
            if (s0 < bestv[i]) { bestv[i] = s0; besti[i] = kbase; }
            if (s1 < bestv[i]) { bestv[i] = s1; besti[i] = kbase + 1; }
            if (s2 < bestv[i]) { bestv[i] = s2; besti[i] = kbase + 2; }
            if (s3 < bestv[i]) { bestv[i] = s3; besti[i] = kbase + 3; }
        }
    }
    __syncthreads();
    float2* red = (float2*)sc;  // 128*16*8B = 16KB, fits in sc
    #pragma unroll
    for (int i = 0; i < 8; i++)
        red[(to0 + i) * 16 + ktid] = make_float2(bestv[i], __int_as_float(besti[i]));
    __syncthreads();
    if (tid < 128) {
        float bv = __int_as_float(0x7f800000);
        int bi = 0x7fffffff;
        #pragma unroll
        for (int m = 0; m < 16; m++) {
            float2 r = red[tid * 16 + m];
            int ri = __float_as_int(r.y);
            if (r.x < bv || (r.x == bv && ri < bi)) { bv = r.x; bi = ri; }
        }
        dout[tokg + tid] = (float)bi;
    }
}

// ============================================================================
// Kernel 4: gather codebook by codes -> quantized_proj region; loss partials.
// grid 256 (128 tokens), block 256.
// ============================================================================
__global__ void k_gather(const float* __restrict__ cbk, float* dout) {
    __shared__ int sidx[128];
    __shared__ float sq[128 * 65];
    __shared__ float rbuf[256];
    int tid = threadIdx.x;
    int tokg = blockIdx.x * 128;
    int b = tokg >> 11;
    int t0g = tokg & (T_ - 1);

    if (tid < 128) sidx[tid] = (int)dout[tokg + tid];
    __syncthreads();
    for (int e = tid; e < 8192; e += 256) {
        int t = e >> 6, c = e & 63;
        sq[t * 65 + c] = cbk[(long long)sidx[t] * CC + c];
    }
    __syncthreads();
    const float* xp = dout + OFF_XPROJ + (long long)b * CC * T_ + t0g;
    float* qp = dout + OFF_QPROJ + (long long)b * CC * T_ + t0g;
    float ls = 0.f;
    for (int e = tid; e < 8192; e += 256) {
        int c = e >> 7, j = e & 127;
        float q = sq[j * 65 + c];
        float d = xp[c * T_ + j] - q;
        ls = fmaf(d, d, ls);
        qp[c * T_ + j] = q;
    }
    rbuf[tid] = ls; __syncthreads();
    for (int st = 128; st >= 1; st >>= 1) {
        if (tid < st) rbuf[tid] += rbuf[tid + st];
        __syncthreads();
    }
    if (tid == 0) g_lossP[blockIdx.x] = rbuf[0];
}

// ============================================================================
// Kernel 5: finalize losses (deterministic tree sum of 256 partials)
// ============================================================================
__global__ void k_loss(float* dout) {
    __shared__ float rb[256];
    int tid = threadIdx.x;
    rb[tid] = g_lossP[tid]; __syncthreads();
    for (int st = 128; st >= 1; st >>= 1) {
        if (tid < st) rb[tid] += rb[tid + st];
        __syncthreads();
    }
    if (tid == 0) {
        float L = rb[0] * (1.f / 2097152.f);  // 2^-21 exact
        dout[OFF_LOSS] = L;
        dout[OFF_LOSS + 1] = L;
    }
}

// ============================================================================
// Kernel 6: quantized = W_out @ quantized_proj (per b: 1024x2048 = 1024x64 @ 64x2048)
// grid (32 t-tiles, 8 o-tiles, 16 b), block 256. Tile 128o x 64t, K=64.
// ============================================================================
__global__ void k_gemm_out(float* dout) {
    __shared__ float sW[64 * 128];  // [c][o]
    __shared__ float sQ[64 * 64];   // [c][t]
    int tid = threadIdx.x;
    int b = blockIdx.z;
    int o0g = blockIdx.y * 128;
    int t0g = blockIdx.x * 64;

    for (int e = tid; e < 8192; e += 256) {
        int c = e >> 7, o = e & 127;
        sW[e] = g_Wout_t[c * CE + o0g + o];
    }
    const float* qp = dout + OFF_QPROJ + (long long)b * CC * T_;
    for (int e = tid; e < 4096; e += 256) {
        int c = e >> 6, t = e & 63;
        sQ[e] = qp[c * T_ + t0g + t];
    }
    __syncthreads();

    int ttid = tid & 15, otid = tid >> 4;
    int o0 = otid * 8, t0 = ttid * 4;
    u64t acc[8][2];
    #pragma unroll
    for (int i = 0; i < 8; i++) { acc[i][0] = 0; acc[i][1] = 0; }
    #pragma unroll 8
    for (int c = 0; c < 64; c++) {
        float4 q4 = *(const float4*)&sQ[c * 64 + t0];
        u64t q0 = pack2(q4.x, q4.y), q1 = pack2(q4.z, q4.w);
        float4 w0 = *(const float4*)&sW[c * 128 + o0];
        float4 w1 = *(const float4*)&sW[c * 128 + o0 + 4];
        float wv[8] = {w0.x, w0.y, w0.z, w0.w, w1.x, w1.y, w1.z, w1.w};
        #pragma unroll
        for (int i = 0; i < 8; i++) {
            u64t wb = pack2(wv[i], wv[i]);
            fma2(acc[i][0], wb, q0);
            fma2(acc[i][1], wb, q1);
        }
    }
    float* outq = dout + OFF_QUANT + (long long)b * CE * T_;
    #pragma unroll
    for (int i = 0; i < 8; i++) {
        float2 a = unpack2(acc[i][0]);
        float2 bb = unpack2(acc[i][1]);
        float4 v = make_float4(a.x, a.y, bb.x, bb.y);
        *(float4*)&outq[(long long)(o0g + o0 + i) * T_ + t0g + t0] = v;
    }
}

// ============================================================================
extern "C" void kernel_launch(void* const* d_in, const int* in_sizes, int n_in,
                              void* d_out, int out_size) {
    const float* x        = (const float*)d_in[0];
    const float* v_in     = (const float*)d_in[1];
    const float* g_in     = (const float*)d_in[2];
    const float* v_out    = (const float*)d_in[3];
    const float* g_out    = (const float*)d_in[4];
    const float* codebook = (const float*)d_in[5];
    float* out = (float*)d_out;

    k_win <<<64, 256>>>(v_in, g_in);
    k_wout<<<128, 256>>>(v_out, g_out);
    k_cbn <<<64, 256>>>(codebook);
    k_gemm_in<<<dim3(16, 16), 256>>>(x, out);
    k_score<<<256, 256>>>(out);
    k_gather<<<256, 256>>>(codebook, out);
    k_loss<<<1, 256>>>(out);
    k_gemm_out<<<dim3(32, 8, 16), 256>>>(out);
}